// round 1
// baseline (speedup 1.0000x reference)
#include <cuda_runtime.h>
#include <cuda_bf16.h>
#include <math.h>

// Scalar accumulator in device global memory (no allocation allowed).
__device__ double g_acc;

__global__ void zero_acc_kernel() {
    g_acc = 0.0;
}

__device__ __forceinline__ void euler_to_R(float a, float b, float c, float* R) {
    // R = Rx(a) @ Ry(b) @ Rz(c)
    float ca = cosf(a), sa = sinf(a);
    float cb = cosf(b), sb = sinf(b);
    float cc = cosf(c), sc = sinf(c);
    R[0] = cb * cc;                R[1] = -cb * sc;               R[2] = sb;
    R[3] = ca * sc + sa * sb * cc; R[4] = ca * cc - sa * sb * sc; R[5] = -sa * cb;
    R[6] = sa * sc - ca * sb * cc; R[7] = sa * cc + ca * sb * sc; R[8] = ca * cb;
}

__global__ __launch_bounds__(256, 8)
void add_loss_kernel(const float* __restrict__ pred,
                     const float* __restrict__ mode,
                     const float* __restrict__ gt,
                     const float* __restrict__ point,
                     int N)  // points per batch row
{
    const int b   = blockIdx.x;
    const int tid = threadIdx.x;

    __shared__ float sRd[9];
    __shared__ double warp_sums[8];

    if (tid == 0) {
        // ---- manifold2euler for pred ----
        float m1 = pred[b * 4 + 0];
        float m2 = pred[b * 4 + 1];
        float m3 = pred[b * 4 + 2];
        float m4 = pred[b * 4 + 3];
        float sgn = (mode[b] > 0.5f) ? 1.0f : -1.0f;
        float denom = m1 * m1 + m2 * m2 + m3 * m3;
        float e2 = sgn * asinf(sqrtf((m3 * m3) / denom));
        float e3 = atan2f(m4, m3 / (sinf(e2) + 1e-9f));
        float tmp = cosf(e2) * cosf(e3);
        float e1 = atan2f(m2 / tmp, m1 / tmp);
        // Note: the reference's "euler3 += 2pi if <= 0" doesn't change cos/sin(e3),
        // so it is irrelevant for the rotation matrix.

        float Rp[9], Rg[9];
        euler_to_R(e1, e2, e3, Rp);
        euler_to_R(gt[b * 3 + 0], gt[b * 3 + 1], gt[b * 3 + 2], Rg);

        #pragma unroll
        for (int i = 0; i < 9; i++) sRd[i] = Rp[i] - Rg[i];
    }
    __syncthreads();

    // Difference matrix in registers (row j, col k): out_k = sum_j p_j * Rd[j][k]
    const float r00 = sRd[0], r01 = sRd[1], r02 = sRd[2];
    const float r10 = sRd[3], r11 = sRd[4], r12 = sRd[5];
    const float r20 = sRd[6], r21 = sRd[7], r22 = sRd[8];

    const float4* pbase = reinterpret_cast<const float4*>(point + (size_t)b * N * 3);

    float sum = 0.0f;
    // Each loop group = 4 points = 3 float4 (fully coalesced 128-bit loads).
    const int ngroups = N >> 2;
    for (int g = tid; g < ngroups; g += blockDim.x) {
        float4 v0 = pbase[3 * g + 0];
        float4 v1 = pbase[3 * g + 1];
        float4 v2 = pbase[3 * g + 2];

        float px, py, pz, x, y, z;

        px = v0.x; py = v0.y; pz = v0.z;
        x = px * r00 + py * r10 + pz * r20;
        y = px * r01 + py * r11 + pz * r21;
        z = px * r02 + py * r12 + pz * r22;
        sum += sqrtf(x * x + y * y + z * z);

        px = v0.w; py = v1.x; pz = v1.y;
        x = px * r00 + py * r10 + pz * r20;
        y = px * r01 + py * r11 + pz * r21;
        z = px * r02 + py * r12 + pz * r22;
        sum += sqrtf(x * x + y * y + z * z);

        px = v1.z; py = v1.w; pz = v2.x;
        x = px * r00 + py * r10 + pz * r20;
        y = px * r01 + py * r11 + pz * r21;
        z = px * r02 + py * r12 + pz * r22;
        sum += sqrtf(x * x + y * y + z * z);

        px = v2.y; py = v2.z; pz = v2.w;
        x = px * r00 + py * r10 + pz * r20;
        y = px * r01 + py * r11 + pz * r21;
        z = px * r02 + py * r12 + pz * r22;
        sum += sqrtf(x * x + y * y + z * z);
    }

    // Warp reduce
    #pragma unroll
    for (int o = 16; o > 0; o >>= 1)
        sum += __shfl_xor_sync(0xFFFFFFFFu, sum, o);

    if ((tid & 31) == 0) warp_sums[tid >> 5] = (double)sum;
    __syncthreads();

    if (tid == 0) {
        double s = 0.0;
        #pragma unroll
        for (int i = 0; i < 8; i++) s += warp_sums[i];
        atomicAdd(&g_acc, s);
    }
}

__global__ void finalize_kernel(float* __restrict__ out, double inv_count) {
    out[0] = (float)(g_acc * inv_count);
}

extern "C" void kernel_launch(void* const* d_in, const int* in_sizes, int n_in,
                              void* d_out, int out_size) {
    const float* pred  = (const float*)d_in[0];   // (B, 4)
    const float* mode  = (const float*)d_in[1];   // (B,)
    const float* gt    = (const float*)d_in[2];   // (B, 3)
    const float* point = (const float*)d_in[3];   // (B, N, 3)

    const int B = in_sizes[1];
    const int N = in_sizes[3] / (B * 3);

    zero_acc_kernel<<<1, 1>>>();
    add_loss_kernel<<<B, 256>>>(pred, mode, gt, point, N);
    finalize_kernel<<<1, 1>>>((float*)d_out, 1.0 / ((double)B * (double)N));
}